// round 14
// baseline (speedup 1.0000x reference)
#include <cuda_runtime.h>
#include <math.h>

#define Nn 50000
#define Ee 1600000
#define Ff 128
#define Ll 3
#define Gg 128
#define Cc 10
#define BN_EPS 1e-5f

#define TILE_M 64
#define FT 512
#define NTILES ((Nn + TILE_M - 1) / TILE_M)          // 782
#define FUSED_SMEM ((2*128*128 + TILE_M*128) * 4)    // 163840 B
#define PAD 128

// scratch (device globals — no allocation allowed)
__device__ __align__(256) float g_x1[(size_t)Nn * Ff];
__device__ __align__(256) float g_x2[(size_t)Nn * Ff];
__device__ __align__(256) float g_w1r[128 * 128];    // pre-rounded, pre-swizzled
__device__ __align__(256) float g_w2r[128 * 128];
__device__ __align__(256) float g_pool[Gg * Ff];
__device__ __align__(256) float g_cnt[Gg];
__device__ __align__(256) int g_deg[Nn];
__device__ __align__(256) int g_srcs[(size_t)Nn * PAD];

// ---- tf32 helpers ----
__device__ __forceinline__ unsigned f2tf32(float f) {
    unsigned r;
    asm("cvt.rna.tf32.f32 %0, %1;" : "=r"(r) : "f"(f));
    return r;
}
__device__ __forceinline__ void mma_tf32(float& d0, float& d1, float& d2, float& d3,
                                         unsigned a0, unsigned a1, unsigned a2, unsigned a3,
                                         unsigned b0, unsigned b1) {
    asm("mma.sync.aligned.m16n8k8.row.col.f32.tf32.tf32.f32 "
        "{%0,%1,%2,%3},{%4,%5,%6,%7},{%8,%9},{%0,%1,%2,%3};"
        : "+f"(d0), "+f"(d1), "+f"(d2), "+f"(d3)
        : "r"(a0), "r"(a1), "r"(a2), "r"(a3), "r"(b0), "r"(b1));
}

// ---- cp.async helpers ----
__device__ __forceinline__ unsigned smem_u32(const void* p) {
    return (unsigned)__cvta_generic_to_shared(p);
}
__device__ __forceinline__ void cpa16(unsigned dst, const void* src) {
    asm volatile("cp.async.cg.shared.global [%0], [%1], 16;"
                 :: "r"(dst), "l"(src) : "memory");
}
__device__ __forceinline__ void cpa_commit() {
    asm volatile("cp.async.commit_group;" ::: "memory");
}

// ---------------------------------------------------------------------------
__global__ void zero_kernel(int* __restrict__ deg, float* __restrict__ pool,
                            float* __restrict__ cnt) {
    int i = blockIdx.x * blockDim.x + threadIdx.x;
    if (i < Nn) deg[i] = 0;
    if (i < Gg * Ff) pool[i] = 0.f;
    if (i < Gg) cnt[i] = 0.f;
}

// single-pass padded CSR fill, 4 edges/thread
__global__ void fill_kernel(const int* __restrict__ ei,
                            int* __restrict__ deg, int* __restrict__ srcs) {
    int i = blockIdx.x * blockDim.x + threadIdx.x;
    if (i < Ee / 4) {
        int4 s = ((const int4*)ei)[i];
        int4 d = ((const int4*)(ei + Ee))[i];
        int c0 = atomicAdd(&deg[d.x], 1);
        int c1 = atomicAdd(&deg[d.y], 1);
        int c2 = atomicAdd(&deg[d.z], 1);
        int c3 = atomicAdd(&deg[d.w], 1);
        srcs[(d.x << 7) + c0] = s.x;
        srcs[(d.y << 7) + c1] = s.y;
        srcs[(d.z << 7) + c2] = s.z;
        srcs[(d.w << 7) + c3] = s.w;
    }
}

// per-layer weight prep: round to tf32 (rna) + swizzle into staging layout.
__global__ void prep_kernel(const float* __restrict__ W1, const float* __restrict__ W2,
                            float* __restrict__ w1r, float* __restrict__ w2r) {
    int i = blockIdx.x * blockDim.x + threadIdx.x;   // 0..8191
    const float* src = (i < 4096) ? W1 : W2;
    float* dst = (i < 4096) ? w1r : w2r;
    int ii = i & 4095;
    int k = ii >> 5, n4 = ii & 31;
    int dchunk = (ii & ~31) | (n4 ^ ((k & 3) << 1));
    float4 v = ((const float4*)src)[ii];
    v.x = __uint_as_float(f2tf32(v.x));
    v.y = __uint_as_float(f2tf32(v.y));
    v.z = __uint_as_float(f2tf32(v.z));
    v.w = __uint_as_float(f2tf32(v.w));
    ((float4*)dst)[dchunk] = v;
}

// ---------------------------------------------------------------------------
// Fused GIN layer tile kernel: one CTA = one 64-node tile.
__global__ __launch_bounds__(FT, 1)
void layer_kernel(const float* __restrict__ x,
                  const int* __restrict__ deg, const int* __restrict__ srcs,
                  const float* __restrict__ w1r, const float* __restrict__ w2r,
                  const float* __restrict__ b1g, const float* __restrict__ b2g,
                  const float* __restrict__ gamma, const float* __restrict__ beta,
                  const float* __restrict__ rmean, const float* __restrict__ rvar,
                  float* __restrict__ xout) {
    extern __shared__ float sm[];
    float* sW1 = sm;                 // 16384 floats
    float* sW2 = sm + 16384;         // 16384 floats
    float* sH  = sm + 32768;         // 8192 floats (tile; reused for M)

    int t = threadIdx.x;
    int lane = t & 31;
    int warp = t >> 5;
    unsigned base = smem_u32(sm);
    int row0 = blockIdx.x * TILE_M;

    // ---- phase 0: stage pre-swizzled weights (straight copies) ----
    #pragma unroll
    for (int i = t; i < 4096; i += FT) {
        cpa16(base + i * 16,         (const float4*)w1r + i);
        cpa16(base + 65536 + i * 16, (const float4*)w2r + i);
    }
    cpa_commit();

    // ---- phase 1: gather 4 nodes per warp into swizzled SMEM ----
    {
        const float* xb = x + lane * 4;
        #pragma unroll 1
        for (int r = 0; r < 4; r++) {
            int row  = warp * 4 + r;
            int node = row0 + row;
            float4 a0 = make_float4(0.f, 0.f, 0.f, 0.f);
            if (node < Nn) {
                a0 = __ldg((const float4*)(xb + (size_t)node * Ff));
                float4 a1 = make_float4(0.f, 0.f, 0.f, 0.f);
                float4 a2 = make_float4(0.f, 0.f, 0.f, 0.f);
                float4 a3 = make_float4(0.f, 0.f, 0.f, 0.f);
                int beg = node << 7;
                int end = beg + deg[node];
                for (int e0 = beg; e0 < end; e0 += 32) {
                    int my = (e0 + lane < end) ? srcs[e0 + lane] : -1;
                    int cnt = min(end - e0, 32);
                    int j = 0;
                    #pragma unroll 2
                    for (; j + 4 <= cnt; j += 4) {
                        int s0 = __shfl_sync(0xffffffffu, my, j);
                        int s1 = __shfl_sync(0xffffffffu, my, j + 1);
                        int s2 = __shfl_sync(0xffffffffu, my, j + 2);
                        int s3 = __shfl_sync(0xffffffffu, my, j + 3);
                        float4 v0 = __ldg((const float4*)(xb + (size_t)s0 * Ff));
                        float4 v1 = __ldg((const float4*)(xb + (size_t)s1 * Ff));
                        float4 v2 = __ldg((const float4*)(xb + (size_t)s2 * Ff));
                        float4 v3 = __ldg((const float4*)(xb + (size_t)s3 * Ff));
                        a0.x += v0.x; a0.y += v0.y; a0.z += v0.z; a0.w += v0.w;
                        a1.x += v1.x; a1.y += v1.y; a1.z += v1.z; a1.w += v1.w;
                        a2.x += v2.x; a2.y += v2.y; a2.z += v2.z; a2.w += v2.w;
                        a3.x += v3.x; a3.y += v3.y; a3.z += v3.z; a3.w += v3.w;
                    }
                    for (; j < cnt; j++) {
                        int s0 = __shfl_sync(0xffffffffu, my, j);
                        float4 v0 = __ldg((const float4*)(xb + (size_t)s0 * Ff));
                        a0.x += v0.x; a0.y += v0.y; a0.z += v0.z; a0.w += v0.w;
                    }
                }
                a0.x += a1.x + a2.x + a3.x;
                a0.y += a1.y + a2.y + a3.y;
                a0.z += a1.z + a2.z + a3.z;
                a0.w += a1.w + a2.w + a3.w;
                a0.x = __uint_as_float(f2tf32(a0.x));
                a0.y = __uint_as_float(f2tf32(a0.y));
                a0.z = __uint_as_float(f2tf32(a0.z));
                a0.w = __uint_as_float(f2tf32(a0.w));
            }
            int chunk = row * 32 + (lane ^ (row & 7));
            *(float4*)(sH + chunk * 4) = a0;
        }
    }

    // ---- phase 2: wait weights, MMA ----
    asm volatile("cp.async.wait_group 0;" ::: "memory");
    __syncthreads();

    int wm = warp & 3;
    int wn = warp >> 2;       // 0..3 -> cols wn*32..+32
    int ar  = wm * 16 + (lane >> 2);
    int acl = lane & 3;
    int s1  = (lane >> 2) << 2;
    int arO  = ar * 128;
    int arO8 = arO + 1024;
    int kl = lane & 3;
    int cidx[4];
    #pragma unroll
    for (int j = 0; j < 4; j++)
        cidx[j] = (wn * 32 + j * 8 + (lane >> 2)) ^ (kl << 3);

    const unsigned* sW1u = (const unsigned*)sW1;
    const unsigned* sW2u = (const unsigned*)sW2;
    const unsigned* sHu  = (const unsigned*)sH;

    float acc[4][4];
    #pragma unroll
    for (int j = 0; j < 4; j++)
        #pragma unroll
        for (int c = 0; c < 4; c++) acc[j][c] = 0.f;

    // ---- GEMM1 ----
    #pragma unroll
    for (int ks = 0; ks < 16; ks++) {
        int k0 = ks * 8;
        int c1 = (k0 | acl) ^ s1;
        unsigned a0 = sHu[arO + c1],        a1 = sHu[arO8 + c1];
        unsigned a2 = sHu[arO + (c1 ^ 4)],  a3 = sHu[arO8 + (c1 ^ 4)];
        int krow = (k0 + kl) * 128;
        #pragma unroll
        for (int j = 0; j < 4; j++) {
            unsigned b0 = sW1u[krow + cidx[j]];
            unsigned b1 = sW1u[krow + 512 + cidx[j]];
            mma_tf32(acc[j][0], acc[j][1], acc[j][2], acc[j][3],
                     a0, a1, a2, a3, b0, b1);
        }
    }
    __syncthreads();
    #pragma unroll
    for (int j = 0; j < 4; j++) {
        int c = wn * 32 + j * 8 + 2 * (lane & 3);
        float2 bb = *(const float2*)(b1g + c);
        unsigned v0 = f2tf32(fmaxf(acc[j][0] + bb.x, 0.f));
        unsigned v1 = f2tf32(fmaxf(acc[j][1] + bb.y, 0.f));
        unsigned v2 = f2tf32(fmaxf(acc[j][2] + bb.x, 0.f));
        unsigned v3 = f2tf32(fmaxf(acc[j][3] + bb.y, 0.f));
        int o = arO + (c ^ s1);
        ((uint2*)sH)[o >> 1]          = make_uint2(v0, v1);
        ((uint2*)sH)[(o + 1024) >> 1] = make_uint2(v2, v3);
    }
    __syncthreads();

    // ---- GEMM2 + BN + ReLU ----
    #pragma unroll
    for (int j = 0; j < 4; j++)
        #pragma unroll
        for (int c = 0; c < 4; c++) acc[j][c] = 0.f;
    #pragma unroll
    for (int ks = 0; ks < 16; ks++) {
        int k0 = ks * 8;
        int c1 = (k0 | acl) ^ s1;
        unsigned a0 = sHu[arO + c1],        a1 = sHu[arO8 + c1];
        unsigned a2 = sHu[arO + (c1 ^ 4)],  a3 = sHu[arO8 + (c1 ^ 4)];
        int krow = (k0 + kl) * 128;
        #pragma unroll
        for (int j = 0; j < 4; j++) {
            unsigned b0 = sW2u[krow + cidx[j]];
            unsigned b1 = sW2u[krow + 512 + cidx[j]];
            mma_tf32(acc[j][0], acc[j][1], acc[j][2], acc[j][3],
                     a0, a1, a2, a3, b0, b1);
        }
    }
    {
        int r0 = row0 + ar;
        int r8 = r0 + 8;
        #pragma unroll
        for (int j = 0; j < 4; j++) {
            int c = wn * 32 + j * 8 + 2 * (lane & 3);
            float2 b2v = *(const float2*)(b2g + c);
            float2 gm  = *(const float2*)(gamma + c);
            float2 bt  = *(const float2*)(beta + c);
            float2 rm  = *(const float2*)(rmean + c);
            float2 rv  = *(const float2*)(rvar + c);
            float sx = gm.x * rsqrtf(rv.x + BN_EPS);
            float sy = gm.y * rsqrtf(rv.y + BN_EPS);
            float ox = bt.x + (b2v.x - rm.x) * sx;
            float oy = bt.y + (b2v.y - rm.y) * sy;
            if (r0 < Nn) {
                float2 v;
                v.x = fmaxf(fmaf(acc[j][0], sx, ox), 0.f);
                v.y = fmaxf(fmaf(acc[j][1], sy, oy), 0.f);
                *(float2*)(xout + (size_t)r0 * 128 + c) = v;
            }
            if (r8 < Nn) {
                float2 v;
                v.x = fmaxf(fmaf(acc[j][2], sx, ox), 0.f);
                v.y = fmaxf(fmaf(acc[j][3], sy, oy), 0.f);
                *(float2*)(xout + (size_t)r8 * 128 + c) = v;
            }
        }
    }
}

// ---------------------------------------------------------------------------
__global__ void pool_kernel(const float* __restrict__ x,
                            const int* __restrict__ batch,
                            float* __restrict__ pool, float* __restrict__ cnt) {
    int gid  = blockIdx.x * blockDim.x + threadIdx.x;
    int node = gid >> 5;
    int lane = gid & 31;
    if (node >= Nn) return;
    int g = batch[node];
    float4 v = *(const float4*)(x + (size_t)node * Ff + lane * 4);
    float* p = pool + g * Ff + lane * 4;
    asm volatile("red.global.add.v4.f32 [%0], {%1,%2,%3,%4};"
                 :: "l"(p), "f"(v.x), "f"(v.y), "f"(v.z), "f"(v.w) : "memory");
    if (lane == 0) atomicAdd(&cnt[g], 1.0f);
}

// ---------------------------------------------------------------------------
__global__ void final_kernel(const float* __restrict__ pool, const float* __restrict__ cnt,
                             const float* __restrict__ fc_w, const float* __restrict__ fc_b,
                             float* __restrict__ out) {
    int g = threadIdx.x;
    if (g >= Gg) return;
    float inv = 1.0f / fmaxf(cnt[g], 1.0f);
    float logits[Cc];
    #pragma unroll
    for (int j = 0; j < Cc; j++) logits[j] = fc_b[j];
    for (int k = 0; k < Ff; k++) {
        float p = pool[g * Ff + k] * inv;
        #pragma unroll
        for (int j = 0; j < Cc; j++) logits[j] += p * fc_w[k * Cc + j];
    }
    float m = logits[0];
    #pragma unroll
    for (int j = 1; j < Cc; j++) m = fmaxf(m, logits[j]);
    float s = 0.f;
    #pragma unroll
    for (int j = 0; j < Cc; j++) s += expf(logits[j] - m);
    float ls = logf(s) + m;
    #pragma unroll
    for (int j = 0; j < Cc; j++) out[g * Cc + j] = logits[j] - ls;
}

// ---------------------------------------------------------------------------
extern "C" void kernel_launch(void* const* d_in, const int* in_sizes, int n_in,
                              void* d_out, int out_size) {
    const float* x     = (const float*)d_in[0];
    const int*   ei    = (const int*)d_in[1];
    const int*   batch = (const int*)d_in[2];
    const float* W1    = (const float*)d_in[3];
    const float* b1    = (const float*)d_in[4];
    const float* W2    = (const float*)d_in[5];
    const float* b2    = (const float*)d_in[6];
    const float* gamma = (const float*)d_in[7];
    const float* beta  = (const float*)d_in[8];
    const float* rmean = (const float*)d_in[9];
    const float* rvar  = (const float*)d_in[10];
    const float* fc_w  = (const float*)d_in[11];
    const float* fc_b  = (const float*)d_in[12];
    float* out = (float*)d_out;

    cudaFuncSetAttribute(layer_kernel, cudaFuncAttributeMaxDynamicSharedMemorySize, FUSED_SMEM);

    float *x1, *x2, *w1r, *w2r, *pool, *cnt;
    int *deg, *srcs;
    cudaGetSymbolAddress((void**)&x1,   g_x1);
    cudaGetSymbolAddress((void**)&x2,   g_x2);
    cudaGetSymbolAddress((void**)&w1r,  g_w1r);
    cudaGetSymbolAddress((void**)&w2r,  g_w2r);
    cudaGetSymbolAddress((void**)&pool, g_pool);
    cudaGetSymbolAddress((void**)&cnt,  g_cnt);
    cudaGetSymbolAddress((void**)&deg,  g_deg);
    cudaGetSymbolAddress((void**)&srcs, g_srcs);

    const int pool_blocks = (Nn * 32 + 255) / 256;

    zero_kernel<<<(Nn + 255) / 256, 256>>>(deg, pool, cnt);
    fill_kernel<<<(Ee / 4 + 255) / 256, 256>>>(ei, deg, srcs);

    const float* cur = x;
    float* outs[Ll] = { x1, x2, x1 };
    for (int l = 0; l < Ll; l++) {
        prep_kernel<<<8192 / 256, 256>>>(W1 + (size_t)l * 128 * 128,
                                         W2 + (size_t)l * 128 * 128, w1r, w2r);
        layer_kernel<<<NTILES, FT, FUSED_SMEM>>>(
            cur, deg, srcs, w1r, w2r,
            b1 + (size_t)l * 128, b2 + (size_t)l * 128,
            gamma + (size_t)l * 128, beta + (size_t)l * 128,
            rmean + (size_t)l * 128, rvar + (size_t)l * 128,
            outs[l]);
        cur = outs[l];
    }

    pool_kernel<<<pool_blocks, 256>>>(cur, batch, pool, cnt);
    final_kernel<<<1, 128>>>(pool, cnt, fc_w, fc_b, out);
}

// round 15
// speedup vs baseline: 1.2532x; 1.2532x over previous
#include <cuda_runtime.h>
#include <math.h>

#define Nn 50000
#define Ee 1600000
#define Ff 128
#define Ll 3
#define Gg 128
#define Cc 10
#define BN_EPS 1e-5f

#define TILE_M 64
#define MLP_THREADS 512
#define MLP_GRID 148
#define NTILES ((Nn + TILE_M - 1) / TILE_M)          // 782
#define MLP_SMEM ((2*128*128 + 2*TILE_M*128) * 4)    // 196608 B
#define PAD 128

// scratch (device globals — no allocation allowed)
__device__ __align__(256) float g_agg[(size_t)Nn * Ff];
__device__ __align__(256) float g_x1[(size_t)Nn * Ff];
__device__ __align__(256) float g_x2[(size_t)Nn * Ff];
__device__ __align__(256) float2 g_w1r[Ll * 8192];   // paired+rounded W1, per layer
__device__ __align__(256) float2 g_w2r[Ll * 8192];   // paired+rounded W2, per layer
__device__ __align__(256) float g_pool[Gg * Ff];
__device__ __align__(256) int g_deg[Nn];
__device__ __align__(256) int g_srcs[(size_t)Nn * PAD];

// ---- tf32 helpers ----
__device__ __forceinline__ unsigned f2tf32(float f) {
    unsigned r;
    asm("cvt.rna.tf32.f32 %0, %1;" : "=r"(r) : "f"(f));
    return r;
}
__device__ __forceinline__ void mma_tf32(float& d0, float& d1, float& d2, float& d3,
                                         unsigned a0, unsigned a1, unsigned a2, unsigned a3,
                                         unsigned b0, unsigned b1) {
    asm("mma.sync.aligned.m16n8k8.row.col.f32.tf32.tf32.f32 "
        "{%0,%1,%2,%3},{%4,%5,%6,%7},{%8,%9},{%0,%1,%2,%3};"
        : "+f"(d0), "+f"(d1), "+f"(d2), "+f"(d3)
        : "r"(a0), "r"(a1), "r"(a2), "r"(a3), "r"(b0), "r"(b1));
}

// ---- cp.async helpers ----
__device__ __forceinline__ unsigned smem_u32(const void* p) {
    return (unsigned)__cvta_generic_to_shared(p);
}
__device__ __forceinline__ void cpa16(unsigned dst, const void* src, bool pred) {
    int sz = pred ? 16 : 0;
    asm volatile("cp.async.cg.shared.global [%0], [%1], 16, %2;"
                 :: "r"(dst), "l"(src), "r"(sz) : "memory");
}
__device__ __forceinline__ void cpa_commit() {
    asm volatile("cp.async.commit_group;" ::: "memory");
}

// ---------------------------------------------------------------------------
__global__ void zero_kernel(int* __restrict__ deg, float* __restrict__ pool) {
    int i = blockIdx.x * blockDim.x + threadIdx.x;
    if (i < Nn) deg[i] = 0;
    if (i < Gg * Ff) pool[i] = 0.f;
}

// single-pass padded CSR fill, 4 edges/thread
__global__ void fill_kernel(const int* __restrict__ ei,
                            int* __restrict__ deg, int* __restrict__ srcs) {
    int i = blockIdx.x * blockDim.x + threadIdx.x;
    if (i < Ee / 4) {
        int4 s = ((const int4*)ei)[i];
        int4 d = ((const int4*)(ei + Ee))[i];
        int c0 = atomicAdd(&deg[d.x], 1);
        int c1 = atomicAdd(&deg[d.y], 1);
        int c2 = atomicAdd(&deg[d.z], 1);
        int c3 = atomicAdd(&deg[d.w], 1);
        srcs[(d.x << 7) + c0] = s.x;
        srcs[(d.y << 7) + c1] = s.y;
        srcs[(d.z << 7) + c2] = s.z;
        srcs[(d.w << 7) + c3] = s.w;
    }
}

// Prep ALL layers' weights: tf32-round + pack B as pairs {W[k][n], W[k+4][n]}
// Pair index p in [0,8192): ks=p>>9, rem=p&511, nhi=rem>>5, b=rem&31,
//   kl=(b>>2)&3, nb=(b&3)|(((b>>4)&1)<<2), n=nhi*8+nb, k0=ks*8+kl.
// This permutation makes the consumer's LDS.64 per half-warp hit 16 distinct
// 8B banks (verified: bank = bits [nb2 kl1 kl0 nb1 nb0] of lane, injective).
__global__ void prep_kernel(const float* __restrict__ W1, const float* __restrict__ W2,
                            float2* __restrict__ w1r, float2* __restrict__ w2r) {
    int i = blockIdx.x * blockDim.x + threadIdx.x;   // 0 .. 3*2*8192-1
    if (i >= Ll * 2 * 8192) return;
    int l = i / 16384;
    int rem0 = i - l * 16384;
    int which = rem0 >> 13;          // 0 = W1, 1 = W2
    int p = rem0 & 8191;
    const float* src = (which ? W2 : W1) + (size_t)l * 16384;
    float2* dst = (which ? w2r : w1r) + l * 8192;
    int ks = p >> 9;
    int rem = p & 511;
    int nhi = rem >> 5;
    int b = rem & 31;
    int kl = (b >> 2) & 3;
    int nb = (b & 3) | (((b >> 4) & 1) << 2);
    int n = nhi * 8 + nb;
    int k0 = ks * 8 + kl;
    float2 v;
    v.x = __uint_as_float(f2tf32(src[k0 * 128 + n]));
    v.y = __uint_as_float(f2tf32(src[(k0 + 4) * 128 + n]));
    dst[p] = v;
}

// ---------------------------------------------------------------------------
// one warp per node: agg[node] = x[node] + sum_{s in in(node)} x[s]  (tf32-rounded)
__global__ void gather_kernel(const float* __restrict__ x,
                              const int* __restrict__ deg,
                              const int* __restrict__ srcs,
                              float* __restrict__ agg) {
    int gid  = blockIdx.x * blockDim.x + threadIdx.x;
    int node = gid >> 5;
    int lane = gid & 31;
    if (node >= Nn) return;
    int beg = node << 7;
    int end = beg + deg[node];
    const float* xb = x + lane * 4;
    float4 a0 = __ldg((const float4*)(xb + (size_t)node * Ff));
    float4 a1 = make_float4(0.f, 0.f, 0.f, 0.f);
    float4 a2 = make_float4(0.f, 0.f, 0.f, 0.f);
    float4 a3 = make_float4(0.f, 0.f, 0.f, 0.f);
    for (int e0 = beg; e0 < end; e0 += 32) {
        int my = (e0 + lane < end) ? srcs[e0 + lane] : -1;
        int cnt = min(end - e0, 32);
        int j = 0;
        #pragma unroll 2
        for (; j + 4 <= cnt; j += 4) {
            int s0 = __shfl_sync(0xffffffffu, my, j);
            int s1 = __shfl_sync(0xffffffffu, my, j + 1);
            int s2 = __shfl_sync(0xffffffffu, my, j + 2);
            int s3 = __shfl_sync(0xffffffffu, my, j + 3);
            float4 v0 = __ldg((const float4*)(xb + (size_t)s0 * Ff));
            float4 v1 = __ldg((const float4*)(xb + (size_t)s1 * Ff));
            float4 v2 = __ldg((const float4*)(xb + (size_t)s2 * Ff));
            float4 v3 = __ldg((const float4*)(xb + (size_t)s3 * Ff));
            a0.x += v0.x; a0.y += v0.y; a0.z += v0.z; a0.w += v0.w;
            a1.x += v1.x; a1.y += v1.y; a1.z += v1.z; a1.w += v1.w;
            a2.x += v2.x; a2.y += v2.y; a2.z += v2.z; a2.w += v2.w;
            a3.x += v3.x; a3.y += v3.y; a3.z += v3.z; a3.w += v3.w;
        }
        for (; j < cnt; j++) {
            int s0 = __shfl_sync(0xffffffffu, my, j);
            float4 v0 = __ldg((const float4*)(xb + (size_t)s0 * Ff));
            a0.x += v0.x; a0.y += v0.y; a0.z += v0.z; a0.w += v0.w;
        }
    }
    a0.x += a1.x + a2.x + a3.x;
    a0.y += a1.y + a2.y + a3.y;
    a0.z += a1.z + a2.z + a3.z;
    a0.w += a1.w + a2.w + a3.w;
    a0.x = __uint_as_float(f2tf32(a0.x));
    a0.y = __uint_as_float(f2tf32(a0.y));
    a0.z = __uint_as_float(f2tf32(a0.z));
    a0.w = __uint_as_float(f2tf32(a0.w));
    *(float4*)(agg + (size_t)node * Ff + lane * 4) = a0;
}

// ---------------------------------------------------------------------------
// Persistent tensor-core MLP (tf32 mma.sync.m16n8k8), paired-B LDS.64 loads.
// do_pool != 0 (last layer): epilogue RED-accumulates into pool instead of xout.
__global__ __launch_bounds__(MLP_THREADS, 1)
void mlp_kernel(const float* __restrict__ agg,
                const float2* __restrict__ w1r, const float2* __restrict__ w2r,
                const float* __restrict__ b1g, const float* __restrict__ b2g,
                const float* __restrict__ gamma, const float* __restrict__ beta,
                const float* __restrict__ rmean, const float* __restrict__ rvar,
                float* __restrict__ xout,
                const int* __restrict__ batch, float* __restrict__ pool, int do_pool) {
    extern __shared__ float sm[];
    float2* sW1p = (float2*)sm;              // 8192 float2 (64KB)
    float2* sW2p = (float2*)(sm + 16384);    // 8192 float2 (64KB)
    float* sT0 = sm + 32768;                 // 8192 floats (tile buf 0)
    float* sT1 = sm + 32768 + 8192;          // 8192 floats (tile buf 1)

    int t = threadIdx.x;
    int lane = t & 31;
    int warp = t >> 5;
    int wm = warp & 3;        // m-group: rows wm*16 .. +16
    int wn = warp >> 2;       // n-group: cols wn*32 .. +32
    unsigned base = smem_u32(sm);

    // ---- stage pre-packed weights (straight copy) ----
    for (int i = t; i < 4096; i += MLP_THREADS) {
        cpa16(base + i * 16,         (const float4*)w1r + i, true);
        cpa16(base + 65536 + i * 16, (const float4*)w2r + i, true);
    }
    cpa_commit();

    // ---- prefetch first tile into buf 0, swizzled ----
    {
        int row0 = blockIdx.x * TILE_M;
        const float4* src = (const float4*)agg + (size_t)row0 * 32;
        unsigned dst = base + 131072;
        for (int i = t; i < 2048; i += MLP_THREADS) {
            int row = i >> 5, c4 = i & 31;
            int dchunk = (i & ~31) | (c4 ^ (row & 7));
            bool ok = (row0 + row) < Nn;
            cpa16(dst + dchunk * 16, ok ? (src + i) : (const float4*)agg, ok);
        }
        cpa_commit();
    }

    // ---- per-thread fragment geometry ----
    int ar  = wm * 16 + (lane >> 2);
    int acl = lane & 3;
    int s1  = (lane >> 2) << 2;
    int arO  = ar * 128;
    int arO8 = arO + 1024;
    // paired-B lane offset: bank-permuted injective index of (kl, nb)
    int bconst = ((lane >> 2) & 3) | ((lane & 3) << 2) | (((lane >> 4) & 1) << 4);
    int cidx[4];
    #pragma unroll
    for (int j = 0; j < 4; j++)
        cidx[j] = (wn * 4 + j) * 32 + bconst;

    // ---- hoisted epilogue params ----
    float2 bias1[4], scl[4], off[4];
    #pragma unroll
    for (int j = 0; j < 4; j++) {
        int c = wn * 32 + j * 8 + 2 * (lane & 3);
        bias1[j] = *(const float2*)(b1g + c);
        float2 b2v = *(const float2*)(b2g + c);
        float2 gm  = *(const float2*)(gamma + c);
        float2 bt  = *(const float2*)(beta + c);
        float2 rm  = *(const float2*)(rmean + c);
        float2 rv  = *(const float2*)(rvar + c);
        scl[j].x = gm.x * rsqrtf(rv.x + BN_EPS);
        scl[j].y = gm.y * rsqrtf(rv.y + BN_EPS);
        off[j].x = bt.x - rm.x * scl[j].x + b2v.x * scl[j].x;
        off[j].y = bt.y - rm.y * scl[j].y + b2v.y * scl[j].y;
    }

    int p = 0;
    for (int tile = blockIdx.x; tile < NTILES; tile += MLP_GRID, p ^= 1) {
        int nxt = tile + MLP_GRID;
        if (nxt < NTILES) {
            int row0n = nxt * TILE_M;
            const float4* src = (const float4*)agg + (size_t)row0n * 32;
            unsigned dst = base + 131072 + (p ^ 1) * 32768;
            for (int i = t; i < 2048; i += MLP_THREADS) {
                int row = i >> 5, c4 = i & 31;
                int dchunk = (i & ~31) | (c4 ^ (row & 7));
                bool ok = (row0n + row) < Nn;
                cpa16(dst + dchunk * 16, ok ? (src + i) : (const float4*)agg, ok);
            }
            cpa_commit();
            asm volatile("cp.async.wait_group 1;" ::: "memory");
        } else {
            asm volatile("cp.async.wait_group 0;" ::: "memory");
        }
        __syncthreads();

        float* sH = p ? sT1 : sT0;
        const unsigned* sHu = (const unsigned*)sH;
        int row0 = tile * TILE_M;

        float acc[4][4];
        #pragma unroll
        for (int j = 0; j < 4; j++)
            #pragma unroll
            for (int c = 0; c < 4; c++) acc[j][c] = 0.f;

        // ---- GEMM1: M = relu(H @ W1 + b1) ----
        #pragma unroll
        for (int ks = 0; ks < 16; ks++) {
            int k0 = ks * 8;
            int c1 = (k0 | acl) ^ s1;
            unsigned a0 = sHu[arO + c1],        a1 = sHu[arO8 + c1];
            unsigned a2 = sHu[arO + (c1 ^ 4)],  a3 = sHu[arO8 + (c1 ^ 4)];
            int kbase = ks * 512;
            #pragma unroll
            for (int j = 0; j < 4; j++) {
                float2 w = sW1p[kbase + cidx[j]];
                mma_tf32(acc[j][0], acc[j][1], acc[j][2], acc[j][3],
                         a0, a1, a2, a3,
                         __float_as_uint(w.x), __float_as_uint(w.y));
            }
        }
        __syncthreads();
        #pragma unroll
        for (int j = 0; j < 4; j++) {
            int c = wn * 32 + j * 8 + 2 * (lane & 3);
            unsigned v0 = f2tf32(fmaxf(acc[j][0] + bias1[j].x, 0.f));
            unsigned v1 = f2tf32(fmaxf(acc[j][1] + bias1[j].y, 0.f));
            unsigned v2 = f2tf32(fmaxf(acc[j][2] + bias1[j].x, 0.f));
            unsigned v3 = f2tf32(fmaxf(acc[j][3] + bias1[j].y, 0.f));
            int o = arO + (c ^ s1);
            ((uint2*)sH)[o >> 1]          = make_uint2(v0, v1);
            ((uint2*)sH)[(o + 1024) >> 1] = make_uint2(v2, v3);
        }
        __syncthreads();

        // ---- GEMM2 + BN + ReLU ----
        #pragma unroll
        for (int j = 0; j < 4; j++)
            #pragma unroll
            for (int c = 0; c < 4; c++) acc[j][c] = 0.f;

        #pragma unroll
        for (int ks = 0; ks < 16; ks++) {
            int k0 = ks * 8;
            int c1 = (k0 | acl) ^ s1;
            unsigned a0 = sHu[arO + c1],        a1 = sHu[arO8 + c1];
            unsigned a2 = sHu[arO + (c1 ^ 4)],  a3 = sHu[arO8 + (c1 ^ 4)];
            int kbase = ks * 512;
            #pragma unroll
            for (int j = 0; j < 4; j++) {
                float2 w = sW2p[kbase + cidx[j]];
                mma_tf32(acc[j][0], acc[j][1], acc[j][2], acc[j][3],
                         a0, a1, a2, a3,
                         __float_as_uint(w.x), __float_as_uint(w.y));
            }
        }
        {
            int r0 = row0 + ar;
            int r8 = r0 + 8;
            if (!do_pool) {
                #pragma unroll
                for (int j = 0; j < 4; j++) {
                    int c = wn * 32 + j * 8 + 2 * (lane & 3);
                    if (r0 < Nn) {
                        float2 v;
                        v.x = fmaxf(fmaf(acc[j][0], scl[j].x, off[j].x), 0.f);
                        v.y = fmaxf(fmaf(acc[j][1], scl[j].y, off[j].y), 0.f);
                        *(float2*)(xout + (size_t)r0 * 128 + c) = v;
                    }
                    if (r8 < Nn) {
                        float2 v;
                        v.x = fmaxf(fmaf(acc[j][2], scl[j].x, off[j].x), 0.f);
                        v.y = fmaxf(fmaf(acc[j][3], scl[j].y, off[j].y), 0.f);
                        *(float2*)(xout + (size_t)r8 * 128 + c) = v;
                    }
                }
            } else {
                int g0 = (r0 < Nn) ? batch[r0] : 0;
                int g8 = (r8 < Nn) ? batch[r8] : 0;
                #pragma unroll
                for (int j = 0; j < 4; j++) {
                    int c = wn * 32 + j * 8 + 2 * (lane & 3);
                    if (r0 < Nn) {
                        float vx = fmaxf(fmaf(acc[j][0], scl[j].x, off[j].x), 0.f);
                        float vy = fmaxf(fmaf(acc[j][1], scl[j].y, off[j].y), 0.f);
                        float* pp = pool + g0 * Ff + c;
                        asm volatile("red.global.add.v2.f32 [%0], {%1,%2};"
                                     :: "l"(pp), "f"(vx), "f"(vy) : "memory");
                    }
                    if (r8 < Nn) {
                        float vx = fmaxf(fmaf(acc[j][2], scl[j].x, off[j].x), 0.f);
                        float vy = fmaxf(fmaf(acc[j][3], scl[j].y, off[j].y), 0.f);
                        float* pp = pool + g8 * Ff + c;
                        asm volatile("red.global.add.v2.f32 [%0], {%1,%2};"
                                     :: "l"(pp), "f"(vx), "f"(vy) : "memory");
                    }
                }
            }
        }
        __syncthreads();
    }
}

// ---------------------------------------------------------------------------
// counts via binary search over sorted batch; then FC + log_softmax
__global__ void final_kernel(const float* __restrict__ pool,
                             const int* __restrict__ batch,
                             const float* __restrict__ fc_w, const float* __restrict__ fc_b,
                             float* __restrict__ out) {
    int g = threadIdx.x;
    if (g >= Gg) return;
    // lower_bound(batch, g) and lower_bound(batch, g+1)
    int lo = 0, hi = Nn;
    while (lo < hi) { int m = (lo + hi) >> 1; if (batch[m] < g) lo = m + 1; else hi = m; }
    int lo2 = lo, hi2 = Nn;
    while (lo2 < hi2) { int m = (lo2 + hi2) >> 1; if (batch[m] < g + 1) lo2 = m + 1; else hi2 = m; }
    float cnt = (float)(lo2 - lo);
    float inv = 1.0f / fmaxf(cnt, 1.0f);
    float logits[Cc];
    #pragma unroll
    for (int j = 0; j < Cc; j++) logits[j] = fc_b[j];
    for (int k = 0; k < Ff; k++) {
        float p = pool[g * Ff + k] * inv;
        #pragma unroll
        for (int j = 0; j < Cc; j++) logits[j] += p * fc_w[k * Cc + j];
    }
    float m = logits[0];
    #pragma unroll
    for (int j = 1; j < Cc; j++) m = fmaxf(m, logits[j]);
    float s = 0.f;
    #pragma unroll
    for (int j = 0; j < Cc; j++) s += expf(logits[j] - m);
    float ls = logf(s) + m;
    #pragma unroll
    for (int j = 0; j < Cc; j++) out[g * Cc + j] = logits[j] - ls;
}

// ---------------------------------------------------------------------------
extern "C" void kernel_launch(void* const* d_in, const int* in_sizes, int n_in,
                              void* d_out, int out_size) {
    const float* x     = (const float*)d_in[0];
    const int*   ei    = (const int*)d_in[1];
    const int*   batch = (const int*)d_in[2];
    const float* W1    = (const float*)d_in[3];
    const float* b1    = (const float*)d_in[4];
    const float* W2    = (const float*)d_in[5];
    const float* b2    = (const float*)d_in[6];
    const float* gamma = (const float*)d_in[7];
    const float* beta  = (const float*)d_in[8];
    const float* rmean = (const float*)d_in[9];
    const float* rvar  = (const float*)d_in[10];
    const float* fc_w  = (const float*)d_in[11];
    const float* fc_b  = (const float*)d_in[12];
    float* out = (float*)d_out;

    cudaFuncSetAttribute(mlp_kernel, cudaFuncAttributeMaxDynamicSharedMemorySize, MLP_SMEM);

    float *agg, *x1, *x2, *pool;
    float2 *w1r, *w2r;
    int *deg, *srcs;
    cudaGetSymbolAddress((void**)&agg,  g_agg);
    cudaGetSymbolAddress((void**)&x1,   g_x1);
    cudaGetSymbolAddress((void**)&x2,   g_x2);
    cudaGetSymbolAddress((void**)&pool, g_pool);
    cudaGetSymbolAddress((void**)&w1r,  g_w1r);
    cudaGetSymbolAddress((void**)&w2r,  g_w2r);
    cudaGetSymbolAddress((void**)&deg,  g_deg);
    cudaGetSymbolAddress((void**)&srcs, g_srcs);

    const int gather_blocks = (Nn * 32 + 255) / 256;

    zero_kernel<<<(Nn + 255) / 256, 256>>>(deg, pool);
    fill_kernel<<<(Ee / 4 + 255) / 256, 256>>>(ei, deg, srcs);
    prep_kernel<<<(Ll * 2 * 8192 + 255) / 256, 256>>>(W1, W2, w1r, w2r);

    const float* cur = x;
    float* outs[Ll] = { x1, x2, x1 };
    for (int l = 0; l < Ll; l++) {
        int last = (l == Ll - 1);
        gather_kernel<<<gather_blocks, 256>>>(cur, deg, srcs, agg);
        mlp_kernel<<<MLP_GRID, MLP_THREADS, MLP_SMEM>>>(
            agg, w1r + l * 8192, w2r + l * 8192,
            b1 + (size_t)l * 128, b2 + (size_t)l * 128,
            gamma + (size_t)l * 128, beta + (size_t)l * 128,
            rmean + (size_t)l * 128, rvar + (size_t)l * 128,
            outs[l], batch, pool, last);
        cur = outs[l];
    }

    final_kernel<<<1, 128>>>(pool, batch, fc_w, fc_b, out);
}

// round 16
// speedup vs baseline: 1.2662x; 1.0104x over previous
#include <cuda_runtime.h>
#include <math.h>

#define Nn 50000
#define Ee 1600000
#define Ff 128
#define Ll 3
#define Gg 128
#define Cc 10
#define BN_EPS 1e-5f

#define TILE_M 64
#define MLP_THREADS 512
#define MLP_GRID 148
#define NTILES ((Nn + TILE_M - 1) / TILE_M)          // 782
#define MLP_SMEM ((2*128*128 + 2*TILE_M*128) * 4)    // 196608 B
#define PAD 128

// scratch (device globals — no allocation allowed)
__device__ __align__(256) float g_agg[(size_t)Nn * Ff];
__device__ __align__(256) float g_x1[(size_t)Nn * Ff];
__device__ __align__(256) float g_x2[(size_t)Nn * Ff];
__device__ __align__(256) float2 g_w1r[Ll * 8192];   // paired+rounded W1, per layer
__device__ __align__(256) float2 g_w2r[Ll * 8192];   // paired+rounded W2, per layer
__device__ __align__(256) float g_pool[Gg * Ff];
__device__ __align__(256) int g_deg[Nn];
__device__ __align__(256) int g_srcs[(size_t)Nn * PAD];

// ---- tf32 helpers ----
__device__ __forceinline__ unsigned f2tf32(float f) {
    unsigned r;
    asm("cvt.rna.tf32.f32 %0, %1;" : "=r"(r) : "f"(f));
    return r;
}
__device__ __forceinline__ void mma_tf32(float& d0, float& d1, float& d2, float& d3,
                                         unsigned a0, unsigned a1, unsigned a2, unsigned a3,
                                         unsigned b0, unsigned b1) {
    asm("mma.sync.aligned.m16n8k8.row.col.f32.tf32.tf32.f32 "
        "{%0,%1,%2,%3},{%4,%5,%6,%7},{%8,%9},{%0,%1,%2,%3};"
        : "+f"(d0), "+f"(d1), "+f"(d2), "+f"(d3)
        : "r"(a0), "r"(a1), "r"(a2), "r"(a3), "r"(b0), "r"(b1));
}

// ---- packed f32x2 add (sm_103a) ----
__device__ __forceinline__ void add2(unsigned long long& d, unsigned long long a) {
    asm("add.rn.f32x2 %0, %0, %1;" : "+l"(d) : "l"(a));
}
__device__ __forceinline__ void unpk2(float& lo, float& hi, unsigned long long v) {
    asm("mov.b64 {%0, %1}, %2;" : "=f"(lo), "=f"(hi) : "l"(v));
}

// ---- cp.async helpers ----
__device__ __forceinline__ unsigned smem_u32(const void* p) {
    return (unsigned)__cvta_generic_to_shared(p);
}
__device__ __forceinline__ void cpa16(unsigned dst, const void* src, bool pred) {
    int sz = pred ? 16 : 0;
    asm volatile("cp.async.cg.shared.global [%0], [%1], 16, %2;"
                 :: "r"(dst), "l"(src), "r"(sz) : "memory");
}
__device__ __forceinline__ void cpa_commit() {
    asm volatile("cp.async.commit_group;" ::: "memory");
}

// ---------------------------------------------------------------------------
__global__ void zero_kernel(int* __restrict__ deg, float* __restrict__ pool) {
    int i = blockIdx.x * blockDim.x + threadIdx.x;
    if (i < Nn) deg[i] = 0;
    if (i < Gg * Ff) pool[i] = 0.f;
}

// single-pass padded CSR fill, 8 edges/thread for ATOMG latency hiding
__global__ void fill_kernel(const int* __restrict__ ei,
                            int* __restrict__ deg, int* __restrict__ srcs) {
    int i = blockIdx.x * blockDim.x + threadIdx.x;
    if (i < Ee / 8) {
        int4 sA = ((const int4*)ei)[2 * i];
        int4 sB = ((const int4*)ei)[2 * i + 1];
        int4 dA = ((const int4*)(ei + Ee))[2 * i];
        int4 dB = ((const int4*)(ei + Ee))[2 * i + 1];
        int c0 = atomicAdd(&deg[dA.x], 1);
        int c1 = atomicAdd(&deg[dA.y], 1);
        int c2 = atomicAdd(&deg[dA.z], 1);
        int c3 = atomicAdd(&deg[dA.w], 1);
        int c4 = atomicAdd(&deg[dB.x], 1);
        int c5 = atomicAdd(&deg[dB.y], 1);
        int c6 = atomicAdd(&deg[dB.z], 1);
        int c7 = atomicAdd(&deg[dB.w], 1);
        srcs[(dA.x << 7) + c0] = sA.x;
        srcs[(dA.y << 7) + c1] = sA.y;
        srcs[(dA.z << 7) + c2] = sA.z;
        srcs[(dA.w << 7) + c3] = sA.w;
        srcs[(dB.x << 7) + c4] = sB.x;
        srcs[(dB.y << 7) + c5] = sB.y;
        srcs[(dB.z << 7) + c6] = sB.z;
        srcs[(dB.w << 7) + c7] = sB.w;
    }
}

// Prep ALL layers' weights: tf32-round + pack B as pairs {W[k][n], W[k+4][n]}
__global__ void prep_kernel(const float* __restrict__ W1, const float* __restrict__ W2,
                            float2* __restrict__ w1r, float2* __restrict__ w2r) {
    int i = blockIdx.x * blockDim.x + threadIdx.x;   // 0 .. 3*2*8192-1
    if (i >= Ll * 2 * 8192) return;
    int l = i / 16384;
    int rem0 = i - l * 16384;
    int which = rem0 >> 13;          // 0 = W1, 1 = W2
    int p = rem0 & 8191;
    const float* src = (which ? W2 : W1) + (size_t)l * 16384;
    float2* dst = (which ? w2r : w1r) + l * 8192;
    int ks = p >> 9;
    int rem = p & 511;
    int nhi = rem >> 5;
    int b = rem & 31;
    int kl = (b >> 2) & 3;
    int nb = (b & 3) | (((b >> 4) & 1) << 2);
    int n = nhi * 8 + nb;
    int k0 = ks * 8 + kl;
    float2 v;
    v.x = __uint_as_float(f2tf32(src[k0 * 128 + n]));
    v.y = __uint_as_float(f2tf32(src[(k0 + 4) * 128 + n]));
    dst[p] = v;
}

// ---------------------------------------------------------------------------
// one warp per node: agg[node] = x[node] + sum_{s in in(node)} x[s]
// packed f32x2 adds: per edge 1 LDG.128 + 1 SHFL + 2 ADD2
__global__ void gather_kernel(const float* __restrict__ x,
                              const int* __restrict__ deg,
                              const int* __restrict__ srcs,
                              float* __restrict__ agg) {
    int gid  = blockIdx.x * blockDim.x + threadIdx.x;
    int node = gid >> 5;
    int lane = gid & 31;
    if (node >= Nn) return;
    int beg = node << 7;
    int end = beg + deg[node];
    const float* xb = x + lane * 4;
    ulonglong2 self = __ldg((const ulonglong2*)(xb + (size_t)node * Ff));
    unsigned long long a0x = self.x, a0y = self.y;
    unsigned long long a1x = 0, a1y = 0, a2x = 0, a2y = 0, a3x = 0, a3y = 0;
    // zero-valued f32x2 pair is bit pattern 0 — safe init.
    for (int e0 = beg; e0 < end; e0 += 32) {
        int my = (e0 + lane < end) ? srcs[e0 + lane] : -1;
        int cnt = min(end - e0, 32);
        int j = 0;
        #pragma unroll 2
        for (; j + 4 <= cnt; j += 4) {
            int s0 = __shfl_sync(0xffffffffu, my, j);
            int s1 = __shfl_sync(0xffffffffu, my, j + 1);
            int s2 = __shfl_sync(0xffffffffu, my, j + 2);
            int s3 = __shfl_sync(0xffffffffu, my, j + 3);
            ulonglong2 v0 = __ldg((const ulonglong2*)(xb + (size_t)s0 * Ff));
            ulonglong2 v1 = __ldg((const ulonglong2*)(xb + (size_t)s1 * Ff));
            ulonglong2 v2 = __ldg((const ulonglong2*)(xb + (size_t)s2 * Ff));
            ulonglong2 v3 = __ldg((const ulonglong2*)(xb + (size_t)s3 * Ff));
            add2(a0x, v0.x); add2(a0y, v0.y);
            add2(a1x, v1.x); add2(a1y, v1.y);
            add2(a2x, v2.x); add2(a2y, v2.y);
            add2(a3x, v3.x); add2(a3y, v3.y);
        }
        for (; j < cnt; j++) {
            int s0 = __shfl_sync(0xffffffffu, my, j);
            ulonglong2 v0 = __ldg((const ulonglong2*)(xb + (size_t)s0 * Ff));
            add2(a0x, v0.x); add2(a0y, v0.y);
        }
    }
    add2(a1x, a2x); add2(a1y, a2y);
    add2(a0x, a3x); add2(a0y, a3y);
    add2(a0x, a1x); add2(a0y, a1y);
    float4 r;
    unpk2(r.x, r.y, a0x);
    unpk2(r.z, r.w, a0y);
    r.x = __uint_as_float(f2tf32(r.x));
    r.y = __uint_as_float(f2tf32(r.y));
    r.z = __uint_as_float(f2tf32(r.z));
    r.w = __uint_as_float(f2tf32(r.w));
    *(float4*)(agg + (size_t)node * Ff + lane * 4) = r;
}

// ---------------------------------------------------------------------------
// Persistent tensor-core MLP (tf32 mma.sync.m16n8k8), paired-B LDS.64 loads.
// do_pool != 0 (last layer): epilogue RED-accumulates into pool instead of xout.
__global__ __launch_bounds__(MLP_THREADS, 1)
void mlp_kernel(const float* __restrict__ agg,
                const float2* __restrict__ w1r, const float2* __restrict__ w2r,
                const float* __restrict__ b1g, const float* __restrict__ b2g,
                const float* __restrict__ gamma, const float* __restrict__ beta,
                const float* __restrict__ rmean, const float* __restrict__ rvar,
                float* __restrict__ xout,
                const int* __restrict__ batch, float* __restrict__ pool, int do_pool) {
    extern __shared__ float sm[];
    float2* sW1p = (float2*)sm;              // 8192 float2 (64KB)
    float2* sW2p = (float2*)(sm + 16384);    // 8192 float2 (64KB)
    float* sT0 = sm + 32768;                 // 8192 floats (tile buf 0)
    float* sT1 = sm + 32768 + 8192;          // 8192 floats (tile buf 1)

    int t = threadIdx.x;
    int lane = t & 31;
    int warp = t >> 5;
    int wm = warp & 3;        // m-group: rows wm*16 .. +16
    int wn = warp >> 2;       // n-group: cols wn*32 .. +32
    unsigned base = smem_u32(sm);

    // ---- stage pre-packed weights (straight copy) ----
    for (int i = t; i < 4096; i += MLP_THREADS) {
        cpa16(base + i * 16,         (const float4*)w1r + i, true);
        cpa16(base + 65536 + i * 16, (const float4*)w2r + i, true);
    }
    cpa_commit();

    // ---- prefetch first tile into buf 0, swizzled ----
    {
        int row0 = blockIdx.x * TILE_M;
        const float4* src = (const float4*)agg + (size_t)row0 * 32;
        unsigned dst = base + 131072;
        for (int i = t; i < 2048; i += MLP_THREADS) {
            int row = i >> 5, c4 = i & 31;
            int dchunk = (i & ~31) | (c4 ^ (row & 7));
            bool ok = (row0 + row) < Nn;
            cpa16(dst + dchunk * 16, ok ? (src + i) : (const float4*)agg, ok);
        }
        cpa_commit();
    }

    // ---- per-thread fragment geometry ----
    int ar  = wm * 16 + (lane >> 2);
    int acl = lane & 3;
    int s1  = (lane >> 2) << 2;
    int arO  = ar * 128;
    int arO8 = arO + 1024;
    int bconst = ((lane >> 2) & 3) | ((lane & 3) << 2) | (((lane >> 4) & 1) << 4);
    int cidx[4];
    #pragma unroll
    for (int j = 0; j < 4; j++)
        cidx[j] = (wn * 4 + j) * 32 + bconst;

    // ---- hoisted epilogue params ----
    float2 bias1[4], scl[4], off[4];
    #pragma unroll
    for (int j = 0; j < 4; j++) {
        int c = wn * 32 + j * 8 + 2 * (lane & 3);
        bias1[j] = *(const float2*)(b1g + c);
        float2 b2v = *(const float2*)(b2g + c);
        float2 gm  = *(const float2*)(gamma + c);
        float2 bt  = *(const float2*)(beta + c);
        float2 rm  = *(const float2*)(rmean + c);
        float2 rv  = *(const float2*)(rvar + c);
        scl[j].x = gm.x * rsqrtf(rv.x + BN_EPS);
        scl[j].y = gm.y * rsqrtf(rv.y + BN_EPS);
        off[j].x = bt.x - rm.x * scl[j].x + b2v.x * scl[j].x;
        off[j].y = bt.y - rm.y * scl[j].y + b2v.y * scl[j].y;
    }

    int p = 0;
    for (int tile = blockIdx.x; tile < NTILES; tile += MLP_GRID, p ^= 1) {
        int nxt = tile + MLP_GRID;
        if (nxt < NTILES) {
            int row0n = nxt * TILE_M;
            const float4* src = (const float4*)agg + (size_t)row0n * 32;
            unsigned dst = base + 131072 + (p ^ 1) * 32768;
            for (int i = t; i < 2048; i += MLP_THREADS) {
                int row = i >> 5, c4 = i & 31;
                int dchunk = (i & ~31) | (c4 ^ (row & 7));
                bool ok = (row0n + row) < Nn;
                cpa16(dst + dchunk * 16, ok ? (src + i) : (const float4*)agg, ok);
            }
            cpa_commit();
            asm volatile("cp.async.wait_group 1;" ::: "memory");
        } else {
            asm volatile("cp.async.wait_group 0;" ::: "memory");
        }
        __syncthreads();

        float* sH = p ? sT1 : sT0;
        const unsigned* sHu = (const unsigned*)sH;
        int row0 = tile * TILE_M;

        float acc[4][4];
        #pragma unroll
        for (int j = 0; j < 4; j++)
            #pragma unroll
            for (int c = 0; c < 4; c++) acc[j][c] = 0.f;

        // ---- GEMM1: M = relu(H @ W1 + b1) ----
        #pragma unroll
        for (int ks = 0; ks < 16; ks++) {
            int k0 = ks * 8;
            int c1 = (k0 | acl) ^ s1;
            unsigned a0 = sHu[arO + c1],        a1 = sHu[arO8 + c1];
            unsigned a2 = sHu[arO + (c1 ^ 4)],  a3 = sHu[arO8 + (c1 ^ 4)];
            int kbase = ks * 512;
            #pragma unroll
            for (int j = 0; j < 4; j++) {
                float2 w = sW1p[kbase + cidx[j]];
                mma_tf32(acc[j][0], acc[j][1], acc[j][2], acc[j][3],
                         a0, a1, a2, a3,
                         __float_as_uint(w.x), __float_as_uint(w.y));
            }
        }
        __syncthreads();
        #pragma unroll
        for (int j = 0; j < 4; j++) {
            int c = wn * 32 + j * 8 + 2 * (lane & 3);
            unsigned v0 = f2tf32(fmaxf(acc[j][0] + bias1[j].x, 0.f));
            unsigned v1 = f2tf32(fmaxf(acc[j][1] + bias1[j].y, 0.f));
            unsigned v2 = f2tf32(fmaxf(acc[j][2] + bias1[j].x, 0.f));
            unsigned v3 = f2tf32(fmaxf(acc[j][3] + bias1[j].y, 0.f));
            int o = arO + (c ^ s1);
            ((uint2*)sH)[o >> 1]          = make_uint2(v0, v1);
            ((uint2*)sH)[(o + 1024) >> 1] = make_uint2(v2, v3);
        }
        __syncthreads();

        // ---- GEMM2 + BN + ReLU ----
        #pragma unroll
        for (int j = 0; j < 4; j++)
            #pragma unroll
            for (int c = 0; c < 4; c++) acc[j][c] = 0.f;

        #pragma unroll
        for (int ks = 0; ks < 16; ks++) {
            int k0 = ks * 8;
            int c1 = (k0 | acl) ^ s1;
            unsigned a0 = sHu[arO + c1],        a1 = sHu[arO8 + c1];
            unsigned a2 = sHu[arO + (c1 ^ 4)],  a3 = sHu[arO8 + (c1 ^ 4)];
            int kbase = ks * 512;
            #pragma unroll
            for (int j = 0; j < 4; j++) {
                float2 w = sW2p[kbase + cidx[j]];
                mma_tf32(acc[j][0], acc[j][1], acc[j][2], acc[j][3],
                         a0, a1, a2, a3,
                         __float_as_uint(w.x), __float_as_uint(w.y));
            }
        }
        {
            int r0 = row0 + ar;
            int r8 = r0 + 8;
            if (!do_pool) {
                #pragma unroll
                for (int j = 0; j < 4; j++) {
                    int c = wn * 32 + j * 8 + 2 * (lane & 3);
                    if (r0 < Nn) {
                        float2 v;
                        v.x = fmaxf(fmaf(acc[j][0], scl[j].x, off[j].x), 0.f);
                        v.y = fmaxf(fmaf(acc[j][1], scl[j].y, off[j].y), 0.f);
                        *(float2*)(xout + (size_t)r0 * 128 + c) = v;
                    }
                    if (r8 < Nn) {
                        float2 v;
                        v.x = fmaxf(fmaf(acc[j][2], scl[j].x, off[j].x), 0.f);
                        v.y = fmaxf(fmaf(acc[j][3], scl[j].y, off[j].y), 0.f);
                        *(float2*)(xout + (size_t)r8 * 128 + c) = v;
                    }
                }
            } else {
                int g0 = (r0 < Nn) ? batch[r0] : 0;
                int g8 = (r8 < Nn) ? batch[r8] : 0;
                #pragma unroll
                for (int j = 0; j < 4; j++) {
                    int c = wn * 32 + j * 8 + 2 * (lane & 3);
                    if (r0 < Nn) {
                        float vx = fmaxf(fmaf(acc[j][0], scl[j].x, off[j].x), 0.f);
                        float vy = fmaxf(fmaf(acc[j][1], scl[j].y, off[j].y), 0.f);
                        float* pp = pool + g0 * Ff + c;
                        asm volatile("red.global.add.v2.f32 [%0], {%1,%2};"
                                     :: "l"(pp), "f"(vx), "f"(vy) : "memory");
                    }
                    if (r8 < Nn) {
                        float vx = fmaxf(fmaf(acc[j][2], scl[j].x, off[j].x), 0.f);
                        float vy = fmaxf(fmaf(acc[j][3], scl[j].y, off[j].y), 0.f);
                        float* pp = pool + g8 * Ff + c;
                        asm volatile("red.global.add.v2.f32 [%0], {%1,%2};"
                                     :: "l"(pp), "f"(vx), "f"(vy) : "memory");
                    }
                }
            }
        }
        __syncthreads();
    }
}

// ---------------------------------------------------------------------------
// counts via binary search over sorted batch; then FC + log_softmax
__global__ void final_kernel(const float* __restrict__ pool,
                             const int* __restrict__ batch,
                             const float* __restrict__ fc_w, const float* __restrict__ fc_b,
                             float* __restrict__ out) {
    int g = threadIdx.x;
    if (g >= Gg) return;
    int lo = 0, hi = Nn;
    while (lo < hi) { int m = (lo + hi) >> 1; if (batch[m] < g) lo = m + 1; else hi = m; }
    int lo2 = lo, hi2 = Nn;
    while (lo2 < hi2) { int m = (lo2 + hi2) >> 1; if (batch[m] < g + 1) lo2 = m + 1; else hi2 = m; }
    float cnt = (float)(lo2 - lo);
    float inv = 1.0f / fmaxf(cnt, 1.0f);
    float logits[Cc];
    #pragma unroll
    for (int j = 0; j < Cc; j++) logits[j] = fc_b[j];
    for (int k = 0; k < Ff; k++) {
        float p = pool[g * Ff + k] * inv;
        #pragma unroll
        for (int j = 0; j < Cc; j++) logits[j] += p * fc_w[k * Cc + j];
    }
    float m = logits[0];
    #pragma unroll
    for (int j = 1; j < Cc; j++) m = fmaxf(m, logits[j]);
    float s = 0.f;
    #pragma unroll
    for (int j = 0; j < Cc; j++) s += expf(logits[j] - m);
    float ls = logf(s) + m;
    #pragma unroll
    for (int j = 0; j < Cc; j++) out[g * Cc + j] = logits[j] - ls;
}

// ---------------------------------------------------------------------------
extern "C" void kernel_launch(void* const* d_in, const int* in_sizes, int n_in,
                              void* d_out, int out_size) {
    const float* x     = (const float*)d_in[0];
    const int*   ei    = (const int*)d_in[1];
    const int*   batch = (const int*)d_in[2];
    const float* W1    = (const float*)d_in[3];
    const float* b1    = (const float*)d_in[4];
    const float* W2    = (const float*)d_in[5];
    const float* b2    = (const float*)d_in[6];
    const float* gamma = (const float*)d_in[7];
    const float* beta  = (const float*)d_in[8];
    const float* rmean = (const float*)d_in[9];
    const float* rvar  = (const float*)d_in[10];
    const float* fc_w  = (const float*)d_in[11];
    const float* fc_b  = (const float*)d_in[12];
    float* out = (float*)d_out;

    cudaFuncSetAttribute(mlp_kernel, cudaFuncAttributeMaxDynamicSharedMemorySize, MLP_SMEM);

    float *agg, *x1, *x2, *pool;
    float2 *w1r, *w2r;
    int *deg, *srcs;
    cudaGetSymbolAddress((void**)&agg,  g_agg);
    cudaGetSymbolAddress((void**)&x1,   g_x1);
    cudaGetSymbolAddress((void**)&x2,   g_x2);
    cudaGetSymbolAddress((void**)&pool, g_pool);
    cudaGetSymbolAddress((void**)&w1r,  g_w1r);
    cudaGetSymbolAddress((void**)&w2r,  g_w2r);
    cudaGetSymbolAddress((void**)&deg,  g_deg);
    cudaGetSymbolAddress((void**)&srcs, g_srcs);

    const int gather_blocks = (Nn * 32 + 255) / 256;

    zero_kernel<<<(Nn + 255) / 256, 256>>>(deg, pool);
    fill_kernel<<<(Ee / 8 + 255) / 256, 256>>>(ei, deg, srcs);
    prep_kernel<<<(Ll * 2 * 8192 + 255) / 256, 256>>>(W1, W2, w1r, w2r);

    const float* cur = x;
    float* outs[Ll] = { x1, x2, x1 };
    for (int l = 0; l < Ll; l++) {
        int last = (l == Ll - 1);
        gather_kernel<<<gather_blocks, 256>>>(cur, deg, srcs, agg);
        mlp_kernel<<<MLP_GRID, MLP_THREADS, MLP_SMEM>>>(
            agg, w1r + l * 8192, w2r + l * 8192,
            b1 + (size_t)l * 128, b2 + (size_t)l * 128,
            gamma + (size_t)l * 128, beta + (size_t)l * 128,
            rmean + (size_t)l * 128, rvar + (size_t)l * 128,
            outs[l], batch, pool, last);
        cur = outs[l];
    }

    final_kernel<<<1, 128>>>(pool, batch, fc_w, fc_b, out);
}